// round 17
// baseline (speedup 1.0000x reference)
#include <cuda_runtime.h>
#include <cuda_bf16.h>
#include <cstdint>

#define WSZ 7
#define SHIFT 3
#define HEADS 16
#define NTOK 49
#define CDIM 512
#define DHEAD 32
#define HH 56
#define NWIN 1024
#define MROWS (NWIN*NTOK)   // 50176
#define NPIX  MROWS

typedef unsigned long long ull;

__device__ unsigned g_xbf[(size_t)NPIX*256];              // x bf16 [pix][512]
__device__ unsigned g_wqkv_t[1536*256];                   // qkv_w^T bf16 [n][k]
__device__ unsigned g_wproj_t[512*256];                   // proj_w^T bf16 [n][k]
__device__ unsigned g_qkvb[(size_t)3*NWIN*HEADS*NTOK*16]; // qkv bf16 [s][win][head][tok][32]
__device__ unsigned g_attnb[(size_t)MROWS*256];           // attn out bf16 [row][512]

__device__ __forceinline__ int row_to_pixel(int r) {
    int win = r / NTOK, t = r - win * NTOK;
    int b  = win >> 6;
    int wy = (win >> 3) & 7;
    int wx = win & 7;
    int ty = t / WSZ, tx = t - ty * WSZ;
    int hs = wy * WSZ + ty;
    int ws = wx * WSZ + tx;
    int h = hs + SHIFT; if (h >= HH) h -= HH;
    int w = ws + SHIFT; if (w >= HH) w -= HH;
    return (b * HH + h) * HH + w;
}

__device__ __forceinline__ unsigned pkbf(float lo, float hi) {
    unsigned r; asm("cvt.rn.bf16x2.f32 %0, %1, %2;" : "=r"(r) : "f"(hi), "f"(lo)); return r;
}
__device__ __forceinline__ unsigned s2u(const void* p) {
    return (unsigned)__cvta_generic_to_shared(p);
}
__device__ __forceinline__ void ldsm4(unsigned* r, unsigned a) {
    asm volatile("ldmatrix.sync.aligned.m8n8.x4.shared.b16 {%0,%1,%2,%3}, [%4];"
                 : "=r"(r[0]), "=r"(r[1]), "=r"(r[2]), "=r"(r[3]) : "r"(a));
}
__device__ __forceinline__ void ldsm4t(unsigned* r, unsigned a) {
    asm volatile("ldmatrix.sync.aligned.m8n8.x4.trans.shared.b16 {%0,%1,%2,%3}, [%4];"
                 : "=r"(r[0]), "=r"(r[1]), "=r"(r[2]), "=r"(r[3]) : "r"(a));
}
__device__ __forceinline__ void mma_bf16(float* d, const unsigned* a, const unsigned* b) {
    asm volatile(
        "mma.sync.aligned.m16n8k16.row.col.f32.bf16.bf16.f32 "
        "{%0,%1,%2,%3}, {%4,%5,%6,%7}, {%8,%9}, {%0,%1,%2,%3};"
        : "+f"(d[0]), "+f"(d[1]), "+f"(d[2]), "+f"(d[3])
        : "r"(a[0]), "r"(a[1]), "r"(a[2]), "r"(a[3]), "r"(b[0]), "r"(b[1]));
}
__device__ __forceinline__ void cp16(unsigned dst, const void* src) {
    asm volatile("cp.async.cg.shared.global [%0], [%1], 16;" :: "r"(dst), "l"(src) : "memory");
}
__device__ __forceinline__ void cp_commit() { asm volatile("cp.async.commit_group;" ::: "memory"); }
__device__ __forceinline__ void cp_wait0()  { asm volatile("cp.async.wait_group 0;" ::: "memory"); }

#define STR 40    // attn smem stride (bf16)
#define STR2 72   // GEMM smem stride for 64-col k-tiles (144B: rows 4 banks apart, 16B aligned)

// ---------------------------------------------------------------------------
// Prepasses
// ---------------------------------------------------------------------------
__global__ void cvt_x_kernel(const float* __restrict__ x) {
    size_t i = (size_t)blockIdx.x * 256 + threadIdx.x;
    float4 v = *reinterpret_cast<const float4*>(x + i * 4);
    uint2 o = { pkbf(v.x, v.y), pkbf(v.z, v.w) };
    *reinterpret_cast<uint2*>(&g_xbf[i * 2]) = o;
}
__global__ void wtrans_kernel(const float* __restrict__ w, int ncols, int which) {
    int n = blockIdx.x, t = threadIdx.x;
    float a = w[(size_t)(2 * t)     * ncols + n];
    float b = w[(size_t)(2 * t + 1) * ncols + n];
    unsigned v = pkbf(a, b);
    if (which) g_wproj_t[n * 256 + t] = v; else g_wqkv_t[n * 256 + t] = v;
}

// ---------------------------------------------------------------------------
// Kernel 1: QKV GEMM. CTA 256x128, 512 threads, warp 64x32, KC=64, 2-stage.
// ---------------------------------------------------------------------------
__global__ __launch_bounds__(512, 1) void qkv_gemm(const float* __restrict__ bias) {
    __shared__ __align__(16) unsigned short As[2][256][STR2];
    __shared__ __align__(16) unsigned short Bs[2][128][STR2];
    __shared__ int rowoff[256];

    const int tid = threadIdx.x;
    const int row0 = blockIdx.y * 256, col0 = blockIdx.x * 128;
    const int lane = tid & 31, wid = tid >> 5;
    const int wm = wid >> 2, wn = wid & 3;

    if (tid < 256) rowoff[tid] = row_to_pixel(row0 + tid) * 256;
    __syncthreads();

    float acc[16][4];
#pragma unroll
    for (int i = 0; i < 16; i++)
#pragma unroll
        for (int j = 0; j < 4; j++) acc[i][j] = 0.0f;

    // staging (k-tile = 64 bf16 = 8 segs of 16B per row)
    const int a_sr = tid >> 1, a_s0 = (tid & 1) * 4;   // A: 4 segs/thread
    const int b_sr = tid >> 2, b_s0 = (tid & 3) * 2;   // B: 2 segs/thread

    auto stage = [&](int buf, int kt) {
        const int k32 = kt * 32;   // uint offset
#pragma unroll
        for (int q = 0; q < 4; q++)
            cp16(s2u(&As[buf][a_sr][(a_s0 + q) * 8]),
                 &g_xbf[(size_t)rowoff[a_sr] + k32 + (a_s0 + q) * 4]);
#pragma unroll
        for (int q = 0; q < 2; q++)
            cp16(s2u(&Bs[buf][b_sr][(b_s0 + q) * 8]),
                 &g_wqkv_t[(size_t)(col0 + b_sr) * 256 + k32 + (b_s0 + q) * 4]);
    };

    stage(0, 0); cp_commit();

    const unsigned a_base = s2u(&As[0][0][0]);
    const unsigned b_base = s2u(&Bs[0][0][0]);
    const unsigned a_sz = 256 * STR2 * 2, b_sz = 128 * STR2 * 2;
    const int a_row = wm * 64 + (lane & 15);
    const int a_colB = (lane >> 4) * 16;
    const int b_row = wn * 32 + ((lane >> 4) & 1) * 8 + (lane & 7);
    const int b_colB = ((lane >> 3) & 1) * 16;

#pragma unroll 1
    for (int t = 0; t < 8; t++) {
        const int buf = t & 1;
        cp_wait0();
        __syncthreads();
        if (t < 7) { stage(buf ^ 1, t + 1); cp_commit(); }
        const unsigned ab = a_base + buf * a_sz;
        const unsigned bb = b_base + buf * b_sz;
#pragma unroll
        for (int ks = 0; ks < 4; ks++) {
            unsigned afr[4][4], bfr[2][4];
#pragma unroll
            for (int mt = 0; mt < 4; mt++)
                ldsm4(afr[mt], ab + (unsigned)((a_row + mt * 16) * (STR2 * 2) + ks * 32 + a_colB));
#pragma unroll
            for (int n2 = 0; n2 < 2; n2++)
                ldsm4(bfr[n2], bb + (unsigned)((b_row + n2 * 16) * (STR2 * 2) + ks * 32 + b_colB));
#pragma unroll
            for (int mt = 0; mt < 4; mt++)
#pragma unroll
                for (int nt = 0; nt < 4; nt++)
                    mma_bf16(acc[mt * 4 + nt], afr[mt], &bfr[nt >> 1][(nt & 1) * 2]);
        }
    }

    // epilogue: +bias, pack bf16, scatter into g_qkvb
#pragma unroll
    for (int mt = 0; mt < 4; mt++) {
#pragma unroll
        for (int half = 0; half < 2; half++) {
            int r = row0 + wm * 64 + mt * 16 + (lane >> 2) + half * 8;
            int win = r / NTOK, tok = r - win * NTOK;
#pragma unroll
            for (int nt = 0; nt < 4; nt++) {
                int c = col0 + wn * 32 + nt * 8 + (lane & 3) * 2;
                int s = c >> 9, head = (c >> 5) & 15, dd = c & 31;
                size_t ub = (((size_t)s * NWIN + win) * HEADS + head) * (NTOK * 16)
                          + (size_t)tok * 16 + (dd >> 1);
                float lo = acc[mt * 4 + nt][half * 2]     + bias[c];
                float hi = acc[mt * 4 + nt][half * 2 + 1] + bias[c + 1];
                g_qkvb[ub] = pkbf(lo, hi);
            }
        }
    }
}

// ---------------------------------------------------------------------------
// Kernel 2: tensor-core windowed attention (unchanged from R14).
// ---------------------------------------------------------------------------
__global__ __launch_bounds__(256) void attn_kernel(const float* __restrict__ table) {
    const int win = blockIdx.x;
    const int hg  = blockIdx.y;
    const int tid = threadIdx.x;
    const int lane = tid & 31, wid = tid >> 5;
    const int hh = wid >> 1;
    const int half = wid & 1;

    __shared__ __align__(16) unsigned short Qs[4][64][STR];
    __shared__ __align__(16) unsigned short Ks[4][64][STR];
    __shared__ __align__(16) unsigned short Vs[4][64][STR];
    __shared__ unsigned short tblh[4][170];
    __shared__ signed char jy7[64], jx7[64], regt[64];

    const size_t SOFF2 = (size_t)NWIN * HEADS * NTOK * 16;

    for (int idx = tid; idx < 720; idx += 256) {
        int arr = idx / 240, rem = idx % 240;
        int h4 = rem / 60, rem2 = rem % 60;
        int row = 49 + rem2 / 4, c = rem2 % 4;
        unsigned short* p = (arr == 0) ? &Qs[h4][row][c * 8]
                          : (arr == 1) ? &Ks[h4][row][c * 8] : &Vs[h4][row][c * 8];
        *reinterpret_cast<uint4*>(p) = make_uint4(0, 0, 0, 0);
    }
    for (int idx = tid; idx < 2352; idx += 256) {
        int arr = idx / 784, rem = idx % 784;
        int h4 = rem / 196, rem2 = rem % 196;
        int row = rem2 / 4, c = rem2 % 4;
        int head = hg * 4 + h4;
        const unsigned* src = &g_qkvb[(size_t)arr * SOFF2
            + (((size_t)win * HEADS + head) * NTOK + row) * 16 + c * 4];
        uint4 v = *reinterpret_cast<const uint4*>(src);
        unsigned short* p = (arr == 0) ? &Qs[h4][row][c * 8]
                          : (arr == 1) ? &Ks[h4][row][c * 8] : &Vs[h4][row][c * 8];
        *reinterpret_cast<uint4*>(p) = v;
    }
    for (int idx = tid; idx < 676; idx += 256) {
        int h4 = idx / 169, e = idx % 169;
        float b = table[e * HEADS + hg * 4 + h4];
        tblh[h4][e] = (unsigned short)(pkbf(b, b) & 0xffffu);
    }
    if (tid < 64) {
        int t = tid;
        if (t < 49) {
            int ty = t / 7, tx = t % 7;
            jy7[t] = (signed char)ty; jx7[t] = (signed char)tx;
            int wy = (win >> 3) & 7, wx = win & 7;
            int hs = wy * 7 + ty, ws = wx * 7 + tx;
            int rh2 = (hs < 49) ? 0 : ((hs < 53) ? 1 : 2);
            int rw2 = (ws < 49) ? 0 : ((ws < 53) ? 1 : 2);
            regt[t] = (signed char)(rh2 * 3 + rw2);
        } else { jy7[t] = 0; jx7[t] = 0; regt[t] = 0; }
    }
    __syncthreads();

    const unsigned short (*Qh)[STR] = Qs[hh];
    const unsigned short (*Kh)[STR] = Ks[hh];
    const unsigned short (*Vh)[STR] = Vs[hh];
    const int r = lane >> 2, cq = lane & 3;

    float sc[2][8][4];
#pragma unroll
    for (int mt = 0; mt < 2; mt++)
#pragma unroll
        for (int nt = 0; nt < 8; nt++)
#pragma unroll
            for (int c = 0; c < 4; c++) sc[mt][nt][c] = 0.0f;

#pragma unroll
    for (int ks = 0; ks < 2; ks++) {
        unsigned afr[2][4], bfr[4][4];
#pragma unroll
        for (int mt = 0; mt < 2; mt++) {
            int arow = (half * 2 + mt) * 16 + (lane & 15);
            ldsm4(afr[mt], s2u(&Qh[arow][ks * 16 + (lane >> 4) * 8]));
        }
#pragma unroll
        for (int p = 0; p < 4; p++) {
            int brow = p * 16 + ((lane >> 4) & 1) * 8 + (lane & 7);
            ldsm4(bfr[p], s2u(&Kh[brow][ks * 16 + ((lane >> 3) & 1) * 8]));
        }
#pragma unroll
        for (int mt = 0; mt < 2; mt++)
#pragma unroll
            for (int nt = 0; nt < 8; nt++)
                mma_bf16(sc[mt][nt], afr[mt], &bfr[nt >> 1][(nt & 1) * 2]);
    }

    const float scale = 0.17677669529663687f;
#pragma unroll
    for (int mt = 0; mt < 2; mt++) {
        const int i0 = (half * 2 + mt) * 16 + r;
#pragma unroll
        for (int rh = 0; rh < 2; rh++) {
            const int i = i0 + rh * 8;
            const int ri = regt[i];
            const int iy = jy7[i], ix = jx7[i];
            float vals[16];
            float mx = -1e30f;
#pragma unroll
            for (int nt = 0; nt < 8; nt++)
#pragma unroll
                for (int cc = 0; cc < 2; cc++) {
                    int j = nt * 8 + cq * 2 + cc;
                    float v;
                    if (j < 49) {
                        int ridx = (iy - jy7[j] + 6) * 13 + (ix - jx7[j] + 6);
                        float b = __uint_as_float((unsigned)tblh[hh][ridx] << 16);
                        float m = (ri != regt[j]) ? -100.0f : 0.0f;
                        v = sc[mt][nt][rh * 2 + cc] * scale + b + m;
                    } else v = -1e30f;
                    vals[nt * 2 + cc] = v;
                    mx = fmaxf(mx, v);
                }
            mx = fmaxf(mx, __shfl_xor_sync(0xffffffffu, mx, 1));
            mx = fmaxf(mx, __shfl_xor_sync(0xffffffffu, mx, 2));
            float sum = 0.0f;
#pragma unroll
            for (int q2 = 0; q2 < 16; q2++) { vals[q2] = __expf(vals[q2] - mx); sum += vals[q2]; }
            sum += __shfl_xor_sync(0xffffffffu, sum, 1);
            sum += __shfl_xor_sync(0xffffffffu, sum, 2);
            float inv = 1.0f / sum;
#pragma unroll
            for (int nt = 0; nt < 8; nt++) {
                sc[mt][nt][rh * 2]     = vals[nt * 2]     * inv;
                sc[mt][nt][rh * 2 + 1] = vals[nt * 2 + 1] * inv;
            }
        }
    }

    unsigned pf[2][4][4];
#pragma unroll
    for (int mt = 0; mt < 2; mt++)
#pragma unroll
        for (int kc = 0; kc < 4; kc++) {
            pf[mt][kc][0] = pkbf(sc[mt][2 * kc][0],     sc[mt][2 * kc][1]);
            pf[mt][kc][1] = pkbf(sc[mt][2 * kc][2],     sc[mt][2 * kc][3]);
            pf[mt][kc][2] = pkbf(sc[mt][2 * kc + 1][0], sc[mt][2 * kc + 1][1]);
            pf[mt][kc][3] = pkbf(sc[mt][2 * kc + 1][2], sc[mt][2 * kc + 1][3]);
        }

    float oc[2][4][4];
#pragma unroll
    for (int mt = 0; mt < 2; mt++)
#pragma unroll
        for (int dt = 0; dt < 4; dt++)
#pragma unroll
            for (int c = 0; c < 4; c++) oc[mt][dt][c] = 0.0f;

#pragma unroll
    for (int kc = 0; kc < 4; kc++) {
        unsigned vfr[2][4];
#pragma unroll
        for (int dp = 0; dp < 2; dp++)
            ldsm4t(vfr[dp], s2u(&Vh[kc * 16 + (lane & 15)][dp * 16 + (lane >> 4) * 8]));
#pragma unroll
        for (int mt = 0; mt < 2; mt++)
#pragma unroll
            for (int dt = 0; dt < 4; dt++)
                mma_bf16(oc[mt][dt], pf[mt][kc], &vfr[dt >> 1][(dt & 1) * 2]);
    }

    const int head = hg * 4 + hh;
#pragma unroll
    for (int mt = 0; mt < 2; mt++) {
        const int i0 = (half * 2 + mt) * 16 + r;
#pragma unroll
        for (int rh = 0; rh < 2; rh++) {
            const int i = i0 + rh * 8;
            if (i < NTOK) {
                size_t rowb = ((size_t)win * NTOK + i) * 256 + head * 16;
#pragma unroll
                for (int dt = 0; dt < 4; dt++)
                    g_attnb[rowb + dt * 4 + cq] = pkbf(oc[mt][dt][rh * 2], oc[mt][dt][rh * 2 + 1]);
            }
        }
    }
}

// ---------------------------------------------------------------------------
// Kernel 3: proj GEMM. CTA 256x128, 512 threads, warp 64x32, KC=64, 2-stage.
// ---------------------------------------------------------------------------
__global__ __launch_bounds__(512, 1) void proj_gemm(const float* __restrict__ x,
                                                    const float* __restrict__ bias,
                                                    float* __restrict__ out) {
    __shared__ __align__(16) unsigned short As[2][256][STR2];
    __shared__ __align__(16) unsigned short Bs[2][128][STR2];

    const int tid = threadIdx.x;
    const int row0 = blockIdx.y * 256, col0 = blockIdx.x * 128;
    const int lane = tid & 31, wid = tid >> 5;
    const int wm = wid >> 2, wn = wid & 3;

    float acc[16][4];
#pragma unroll
    for (int i = 0; i < 16; i++)
#pragma unroll
        for (int j = 0; j < 4; j++) acc[i][j] = 0.0f;

    const int a_sr = tid >> 1, a_s0 = (tid & 1) * 4;
    const int b_sr = tid >> 2, b_s0 = (tid & 3) * 2;

    auto stage = [&](int buf, int kt) {
        const int k32 = kt * 32;
#pragma unroll
        for (int q = 0; q < 4; q++)
            cp16(s2u(&As[buf][a_sr][(a_s0 + q) * 8]),
                 &g_attnb[(size_t)(row0 + a_sr) * 256 + k32 + (a_s0 + q) * 4]);
#pragma unroll
        for (int q = 0; q < 2; q++)
            cp16(s2u(&Bs[buf][b_sr][(b_s0 + q) * 8]),
                 &g_wproj_t[(size_t)(col0 + b_sr) * 256 + k32 + (b_s0 + q) * 4]);
    };

    stage(0, 0); cp_commit();

    const unsigned a_base = s2u(&As[0][0][0]);
    const unsigned b_base = s2u(&Bs[0][0][0]);
    const unsigned a_sz = 256 * STR2 * 2, b_sz = 128 * STR2 * 2;
    const int a_row = wm * 64 + (lane & 15);
    const int a_colB = (lane >> 4) * 16;
    const int b_row = wn * 32 + ((lane >> 4) & 1) * 8 + (lane & 7);
    const int b_colB = ((lane >> 3) & 1) * 16;

#pragma unroll 1
    for (int t = 0; t < 8; t++) {
        const int buf = t & 1;
        cp_wait0();
        __syncthreads();
        if (t < 7) { stage(buf ^ 1, t + 1); cp_commit(); }
        const unsigned ab = a_base + buf * a_sz;
        const unsigned bb = b_base + buf * b_sz;
#pragma unroll
        for (int ks = 0; ks < 4; ks++) {
            unsigned afr[4][4], bfr[2][4];
#pragma unroll
            for (int mt = 0; mt < 4; mt++)
                ldsm4(afr[mt], ab + (unsigned)((a_row + mt * 16) * (STR2 * 2) + ks * 32 + a_colB));
#pragma unroll
            for (int n2 = 0; n2 < 2; n2++)
                ldsm4(bfr[n2], bb + (unsigned)((b_row + n2 * 16) * (STR2 * 2) + ks * 32 + b_colB));
#pragma unroll
            for (int mt = 0; mt < 4; mt++)
#pragma unroll
                for (int nt = 0; nt < 4; nt++)
                    mma_bf16(acc[mt * 4 + nt], afr[mt], &bfr[nt >> 1][(nt & 1) * 2]);
        }
    }

#pragma unroll
    for (int mt = 0; mt < 4; mt++) {
#pragma unroll
        for (int half = 0; half < 2; half++) {
            int r = row0 + wm * 64 + mt * 16 + (lane >> 2) + half * 8;
            size_t pix = (size_t)row_to_pixel(r) * CDIM;
#pragma unroll
            for (int nt = 0; nt < 4; nt++) {
                int c = col0 + wn * 32 + nt * 8 + (lane & 3) * 2;
                float2 bv2 = *reinterpret_cast<const float2*>(bias + c);
                float2 xv  = *reinterpret_cast<const float2*>(x + pix + c);
                float2 ov;
                ov.x = xv.x + acc[mt * 4 + nt][half * 2]     + bv2.x;
                ov.y = xv.y + acc[mt * 4 + nt][half * 2 + 1] + bv2.y;
                *reinterpret_cast<float2*>(&out[pix + c]) = ov;
            }
        }
    }
}

extern "C" void kernel_launch(void* const* d_in, const int* in_sizes, int n_in,
                              void* d_out, int out_size) {
    const float* x      = (const float*)d_in[0];
    const float* qkv_w  = (const float*)d_in[1];
    const float* qkv_b  = (const float*)d_in[2];
    const float* proj_w = (const float*)d_in[3];
    const float* proj_b = (const float*)d_in[4];
    const float* table  = (const float*)d_in[5];
    float* out = (float*)d_out;

    cvt_x_kernel<<<(NPIX * 512 / 4) / 256, 256>>>(x);
    wtrans_kernel<<<1536, 256>>>(qkv_w, 1536, 0);
    wtrans_kernel<<<512, 256>>>(proj_w, 512, 1);

    qkv_gemm<<<dim3(12, 196), 512>>>(qkv_b);
    attn_kernel<<<dim3(NWIN, 4), 256>>>(table);
    proj_gemm<<<dim3(4, 196), 512>>>(x, proj_b, out);
}